// round 1
// baseline (speedup 1.0000x reference)
#include <cuda_runtime.h>

// Janossy pooling, k=2, n=2048, d=32.
// out[0][d] = sum_i X[i][d] * (n-1-rank_i) / C(n,2)
// out[1][d] = sum_i X[i][d] * rank_i       / C(n,2)
// rank_i = stable rank of X[i][0] (ties broken by original index, matching
// jnp.argsort's stable sort).

#define NROWS 2048
#define NDIM  32
#define BLOCK 512               // 16 warps -> 16 rows per block
#define GRID  (NROWS / 16)      // 128 blocks, one wave on 148 SMs

__device__ float g_keys[NROWS];

// Compact keys (stride-32 gather done once) and zero the output accumulator.
__global__ void janossy_prep(const float* __restrict__ X, float* __restrict__ out) {
    int i = blockIdx.x * blockDim.x + threadIdx.x;
    if (i < NROWS) g_keys[i] = X[i * NDIM];
    if (i < 2 * NDIM) out[i] = 0.0f;
}

__global__ __launch_bounds__(BLOCK) void janossy_main(const float* __restrict__ X,
                                                      float* __restrict__ out) {
    __shared__ float skeys[NROWS];
    __shared__ float sacc[2 * NDIM];

    const int tid  = threadIdx.x;
    const int warp = tid >> 5;
    const int lane = tid & 31;

    // Stage all keys into shared memory (coalesced from dense g_keys).
    #pragma unroll
    for (int t = tid; t < NROWS; t += BLOCK) skeys[t] = g_keys[t];
    if (tid < 2 * NDIM) sacc[tid] = 0.0f;
    __syncthreads();

    // One warp per row.
    const int row = blockIdx.x * 16 + warp;
    const float xi = skeys[row];          // broadcast read

    int cnt = 0;
    #pragma unroll
    for (int m = 0; m < NROWS / 32; m++) {
        const int j = lane + m * 32;      // bank-conflict-free
        const float kj = skeys[j];
        // strictly-less, ties broken by index (stable sort semantics)
        cnt += (int)(kj < xi) | ((int)(kj == xi) & (int)(j < row));
    }
    const int r = __reduce_add_sync(0xffffffffu, cnt);   // rank, all lanes

    // Weighted contribution of this row; lane == feature dim (NDIM == 32).
    const float invC = 1.0f / 2096128.0f;  // 1 / C(2048,2)
    const float x  = X[row * NDIM + lane]; // coalesced 128B row read
    const float w1 = (float)r * invC;
    const float w0 = (float)(NROWS - 1 - r) * invC;

    atomicAdd(&sacc[lane],        x * w0);
    atomicAdd(&sacc[NDIM + lane], x * w1);
    __syncthreads();

    if (tid < 2 * NDIM) atomicAdd(&out[tid], sacc[tid]);
}

extern "C" void kernel_launch(void* const* d_in, const int* in_sizes, int n_in,
                              void* d_out, int out_size) {
    const float* X = (const float*)d_in[0];
    float* out = (float*)d_out;

    janossy_prep<<<(NROWS + 255) / 256, 256>>>(X, out);
    janossy_main<<<GRID, BLOCK>>>(X, out);
}